// round 13
// baseline (speedup 1.0000x reference)
#include <cuda_runtime.h>
#include <cuda_fp16.h>
#include <cuda_bf16.h>
#include <cstdint>

#define B_    8
#define CTXN  4096
#define QSTN  512
#define E_DIM 300
#define EPAD  320
#define H_DIM 128
#define L2E   1.44269504088896340736f

// f16 qst logits, [q,h] layout (1 MB)
__device__ __align__(16) __half g_Q[B_ * QSTN * H_DIM];

// ---------------------------------------------------------------------------
// helpers
// ---------------------------------------------------------------------------
__device__ __forceinline__ uint32_t smem_u32(const void* p) {
    uint32_t a;
    asm("{ .reg .u64 t; cvta.to.shared.u64 t, %1; cvt.u32.u64 %0, t; }" : "=r"(a) : "l"(p));
    return a;
}
__device__ __forceinline__ void ldsm4(uint32_t* r, uint32_t addr) {
    asm volatile("ldmatrix.sync.aligned.m8n8.x4.shared.b16 {%0,%1,%2,%3}, [%4];"
                 : "=r"(r[0]), "=r"(r[1]), "=r"(r[2]), "=r"(r[3]) : "r"(addr));
}
__device__ __forceinline__ void ldsm4t(uint32_t* r, uint32_t addr) {
    asm volatile("ldmatrix.sync.aligned.m8n8.x4.trans.shared.b16 {%0,%1,%2,%3}, [%4];"
                 : "=r"(r[0]), "=r"(r[1]), "=r"(r[2]), "=r"(r[3]) : "r"(addr));
}
__device__ __forceinline__ void mma_f16(float* c, const uint32_t* a, const uint32_t* b) {
    asm volatile("mma.sync.aligned.m16n8k16.row.col.f32.f16.f16.f32 "
                 "{%0,%1,%2,%3}, {%4,%5,%6,%7}, {%8,%9}, {%0,%1,%2,%3};"
                 : "+f"(c[0]), "+f"(c[1]), "+f"(c[2]), "+f"(c[3])
                 : "r"(a[0]), "r"(a[1]), "r"(a[2]), "r"(a[3]), "r"(b[0]), "r"(b[1]));
}
__device__ __forceinline__ float ex2f(float x) {
    float y; asm("ex2.approx.f32 %0, %1;" : "=f"(y) : "f"(x)); return y;
}
__device__ __forceinline__ void cpa16(uint32_t dst, const void* src) {
    asm volatile("cp.async.cg.shared.global [%0], [%1], 16;" :: "r"(dst), "l"(src));
}
#define CP_COMMIT() asm volatile("cp.async.commit_group;")

// split float4 into packed f16 hi/lo (2x uint2)
__device__ __forceinline__ void split4h(float4 v, uint2& hv, uint2& lv) {
    float t[4] = {v.x, v.y, v.z, v.w};
    uint32_t hh[2], ll[2];
#pragma unroll
    for (int p = 0; p < 2; p++) {
        __half a = __float2half_rn(t[2 * p]);
        __half c = __float2half_rn(t[2 * p + 1]);
        __half2 h2; h2.x = a; h2.y = c;
        __half2 l2;
        l2.x = __float2half_rn(t[2 * p] - __half2float(a));
        l2.y = __float2half_rn(t[2 * p + 1] - __half2float(c));
        hh[p] = *reinterpret_cast<uint32_t*>(&h2);
        ll[p] = *reinterpret_cast<uint32_t*>(&l2);
    }
    hv = make_uint2(hh[0], hh[1]);
    lv = make_uint2(ll[0], ll[1]);
}

// convert float4 -> packed f16 (uint2)
__device__ __forceinline__ uint2 cvt4h(float4 v) {
    __half2 h0 = __floats2half2_rn(v.x, v.y);
    __half2 h1 = __floats2half2_rn(v.z, v.w);
    return make_uint2(*reinterpret_cast<uint32_t*>(&h0),
                      *reinterpret_cast<uint32_t*>(&h1));
}

// ---------------------------------------------------------------------------
// Kernel 1: qst logits via HMMA (f16 A-split 2-pass). 1 CTA = 32 q-rows, 8 warps.
// (unchanged from R12)
// ---------------------------------------------------------------------------
#define WPITCH 656
#define OFF1_A 0
#define OFF1_W 41984
#define OFF1_T 125952
#define SM1_BYTES 134656
#define K1_TP 136

__global__ __launch_bounds__(256, 1)
void qst_logits_kernel(const float* __restrict__ qst,
                       const float* __restrict__ W,
                       const float* __restrict__ bias) {
    extern __shared__ char sm[];
    const uint32_t base = smem_u32(sm);
    const int tid = threadIdx.x, w = tid >> 5, l = tid & 31;
    const int s = w & 1, c = w >> 1;
    const int grp = l >> 2, qd = l & 3;
    const int asel = (l >> 4) & 1, bsel = (l >> 3) & 1, brow = l & 7;
    const int row0 = blockIdx.x * 32;

#pragma unroll
    for (int it = 0; it < 40; it++) {
        int idx = tid + it * 256;
        int row = idx / 80, seg = idx - row * 80;
        float4 v = make_float4(0.f, 0.f, 0.f, 0.f);
        if (seg < 75)
            v = *(const float4*)(W + (size_t)row * E_DIM + seg * 4);
        *(uint2*)(sm + OFF1_W + row * WPITCH + seg * 8) = cvt4h(v);
    }

#pragma unroll
    for (int it = 0; it < 10; it++) {
        int idx = tid + it * 256;
        int row = idx / 80, seg = idx - row * 80;
        float4 v = make_float4(0.f, 0.f, 0.f, 0.f);
        if (seg < 75)
            v = *(const float4*)(qst + (size_t)(row0 + row) * E_DIM + seg * 4);
        uint2 hv, lv;
        split4h(v, hv, lv);
        *(uint2*)(sm + OFF1_A + row * WPITCH + seg * 8) = hv;
        *(uint2*)(sm + OFF1_A + 20992 + row * WPITCH + seg * 8) = lv;
    }
    __syncthreads();

    float acc[4][4];
#pragma unroll
    for (int j = 0; j < 4; j++)
#pragma unroll
        for (int i = 0; i < 4; i++) acc[j][i] = 0.f;

    const uint32_t arow = (uint32_t)(s * 16 + (l & 15));
#pragma unroll
    for (int kk = 0; kk < 19; kk++) {
        uint32_t Ah[4], Al[4];
        uint32_t aoff = arow * WPITCH + (uint32_t)((kk * 16 + asel * 8) * 2);
        ldsm4(Ah, base + OFF1_A + aoff);
        ldsm4(Al, base + OFF1_A + 20992 + aoff);
#pragma unroll
        for (int jp = 0; jp < 2; jp++) {
            uint32_t Bw[4];
            uint32_t boff = (uint32_t)((c * 32 + 16 * jp + 8 * asel + brow) * WPITCH
                                       + (kk * 16 + bsel * 8) * 2);
            ldsm4(Bw, base + OFF1_W + boff);
            mma_f16(acc[2 * jp],     Ah, Bw);
            mma_f16(acc[2 * jp],     Al, Bw);
            mma_f16(acc[2 * jp + 1], Ah, Bw + 2);
            mma_f16(acc[2 * jp + 1], Al, Bw + 2);
        }
    }

    __half* sT = (__half*)(sm + OFF1_T);
    const int rowa = s * 16 + grp;
#pragma unroll
    for (int j = 0; j < 4; j++) {
        int col = c * 32 + 8 * j + 2 * qd;
        float b0 = bias[col], b1 = bias[col + 1];
        sT[rowa * K1_TP + col]     = __float2half_rn(fmaxf(acc[j][0] + b0, 0.f));
        sT[rowa * K1_TP + col + 1] = __float2half_rn(fmaxf(acc[j][1] + b1, 0.f));
        sT[(rowa + 8) * K1_TP + col]     = __float2half_rn(fmaxf(acc[j][2] + b0, 0.f));
        sT[(rowa + 8) * K1_TP + col + 1] = __float2half_rn(fmaxf(acc[j][3] + b1, 0.f));
    }
    __syncthreads();

    for (int idx = tid; idx < 32 * 16; idx += 256) {
        int r = idx >> 4, seg = idx & 15;
        uint4 v = *(uint4*)(sT + r * K1_TP + seg * 8);
        *(uint4*)(g_Q + (size_t)(row0 + r) * H_DIM + seg * 8) = v;
    }
}

// ---------------------------------------------------------------------------
// Kernel 2: HMMA fused dense + flash attention. 1 CTA = 128 ctx rows, 16 warps.
// Warp (s,c): 16-row strip s (0-7), 64-col half c (0-1). L/P via smem exchange.
// ---------------------------------------------------------------------------
#define OFF_BIAS 0          // 512B
#define OFF_MADD 512        // 2048B -> 2560
#define OFF_RMAX 2560       // 1024B -> 3584
#define OFF_RSUM 3584       // 1024B -> 4608
#define OFF_A    4864       // ctx hi 18432, lo +18432 -> end 41728
#define OFF_W    41728      // W f16 83968 -> end 125696
#define OFF_F0   4864       // flash buf0 (34816)
#define OFF_F1   39680      // flash buf1 -> 74496
#define OFF_P    74496      // L/P exchange tile (34816) -> 109312
#define SM2_BYTES 125696

__global__ __launch_bounds__(512, 1)
void attn_kernel(const float* __restrict__ ctx,
                 const int* __restrict__ mask,
                 const float* __restrict__ W,
                 const float* __restrict__ bias,
                 float* __restrict__ out) {
    extern __shared__ char sm[];
    const uint32_t base = smem_u32(sm);
    const int tid = threadIdx.x, w = tid >> 5, l = tid & 31;
    const int s = w & 7, c = w >> 3;
    const int grp = l >> 2, qd = l & 3;
    const int asel = (l >> 4) & 1, bsel = (l >> 3) & 1, brow = l & 7;
    const int b = blockIdx.y, c0 = blockIdx.x * 128;

    // whole W converted float->f16 into smem (L2-hot after first CTA)
#pragma unroll
    for (int it = 0; it < 20; it++) {
        int idx = tid + it * 512;
        int row = idx / 80, seg = idx - row * 80;
        float4 v = make_float4(0.f, 0.f, 0.f, 0.f);
        if (seg < 75)
            v = *(const float4*)(W + (size_t)row * E_DIM + seg * 4);
        *(uint2*)(sm + OFF_W + row * WPITCH + seg * 8) = cvt4h(v);
    }

    float* biasSm = (float*)(sm + OFF_BIAS);
    float* maddSm = (float*)(sm + OFF_MADD);
    float* rmaxSm = (float*)(sm + OFF_RMAX);
    float* rsumSm = (float*)(sm + OFF_RSUM);
    for (int i = tid; i < H_DIM; i += 512) biasSm[i] = bias[i];
    for (int i = tid; i < QSTN; i += 512)
        maddSm[i] = mask[b * QSTN + i] ? 0.f : -2e30f;

    const float* ctxb = ctx + ((size_t)b * CTXN + c0) * E_DIM;

    // prefetch ctx chunk 0
    float4 pa[4];
#pragma unroll
    for (int it = 0; it < 4; it++) {
        int idx = tid + it * 512;
        int row = idx >> 4, c4 = idx & 15;
        pa[it] = *(const float4*)(ctxb + (size_t)row * E_DIM + c4 * 4);
    }

    // ---------------- Phase 1: acc = ctx_tile @ W^T (f16 A-split 2-pass) ----
    float acc[8][4];
#pragma unroll
    for (int j = 0; j < 8; j++)
#pragma unroll
        for (int i = 0; i < 4; i++) acc[j][i] = 0.f;

    const uint32_t arow = (uint32_t)(s * 16 + (l & 15));

    for (int ck = 0; ck < 5; ck++) {
        __syncthreads();
#pragma unroll
        for (int it = 0; it < 4; it++) {
            int idx = tid + it * 512;
            int row = idx >> 4, c4 = idx & 15;
            uint2 hv, lv;
            split4h(pa[it], hv, lv);
            *(uint2*)(sm + OFF_A + row * 144 + c4 * 8) = hv;
            *(uint2*)(sm + OFF_A + 18432 + row * 144 + c4 * 8) = lv;
        }
        if (ck < 4) {
#pragma unroll
            for (int it = 0; it < 4; it++) {
                int idx = tid + it * 512;
                int row = idx >> 4, c4 = idx & 15;
                float4 v = make_float4(0.f, 0.f, 0.f, 0.f);
                if (ck < 3 || c4 < 11)
                    v = *(const float4*)(ctxb + (size_t)row * E_DIM + (ck + 1) * 64 + c4 * 4);
                pa[it] = v;
            }
        }
        __syncthreads();

        const int nks = (ck < 4) ? 4 : 3;    // skip all-zero cols 304-319
#pragma unroll
        for (int kk = 0; kk < 4; kk++) {
            if (kk >= nks) break;
            const int gk = ck * 4 + kk;
            uint32_t Ah[4], Al[4];
            uint32_t aoff = arow * 144 + (uint32_t)((kk * 16 + asel * 8) * 2);
            ldsm4(Ah, base + OFF_A + aoff);
            ldsm4(Al, base + OFF_A + 18432 + aoff);
#pragma unroll
            for (int jp = 0; jp < 4; jp++) {
                uint32_t Bw[4];
                uint32_t boff = (uint32_t)((c * 64 + 16 * jp + 8 * asel + brow) * WPITCH
                                           + (gk * 16 + bsel * 8) * 2);
                ldsm4(Bw, base + OFF_W + boff);
                mma_f16(acc[2 * jp],     Ah, Bw);
                mma_f16(acc[2 * jp],     Al, Bw);
                mma_f16(acc[2 * jp + 1], Ah, Bw + 2);
                mma_f16(acc[2 * jp + 1], Al, Bw + 2);
            }
        }
    }
    __syncthreads();

    // ---------------- bias + relu -> L smem (f16), then Lf a-frags ----------
    const int rowa = s * 16 + grp;
#pragma unroll
    for (int j = 0; j < 8; j++) {
        int col = c * 64 + 8 * j + 2 * qd;
        float2 bb = *(float2*)(biasSm + col);
        __half2 v0 = __floats2half2_rn(fmaxf(acc[j][0] + bb.x, 0.f),
                                       fmaxf(acc[j][1] + bb.y, 0.f));
        __half2 v1 = __floats2half2_rn(fmaxf(acc[j][2] + bb.x, 0.f),
                                       fmaxf(acc[j][3] + bb.y, 0.f));
        *(__half2*)(sm + OFF_P + rowa * 272 + col * 2) = v0;
        *(__half2*)(sm + OFF_P + (rowa + 8) * 272 + col * 2) = v1;
    }
    __syncthreads();

    uint32_t Lf[8][4];
#pragma unroll
    for (int kk = 0; kk < 8; kk++)
        ldsm4(Lf[kk], base + OFF_P + (uint32_t)((s * 16 + (l & 15)) * 272
                                                + (kk * 16 + asel * 8) * 2));

    // ---------------- Flash loop: cp.async double-buffered Q tiles ----------
    const __half* gq = g_Q + (size_t)b * QSTN * H_DIM;

#pragma unroll
    for (int t0 = 0; t0 < 2; t0++) {
        uint32_t buf = base + (t0 ? OFF_F1 : OFF_F0);
#pragma unroll
        for (int it = 0; it < 4; it++) {
            int idx = tid + it * 512;
            int row = idx >> 4, seg = idx & 15;
            cpa16(buf + row * 272 + seg * 16,
                  gq + (size_t)(t0 * 128 + row) * H_DIM + seg * 8);
        }
        CP_COMMIT();
    }

    float m2a = -1e30f, m2b = -1e30f, sra = 0.f, srb = 0.f;
    float o_acc[8][4];
#pragma unroll
    for (int j = 0; j < 8; j++)
#pragma unroll
        for (int i = 0; i < 4; i++) o_acc[j][i] = 0.f;

    for (int t = 0; t < 4; t++) {
        if (t < 3) asm volatile("cp.async.wait_group 1;");
        else       asm volatile("cp.async.wait_group 0;");
        __syncthreads();
        const uint32_t bufQ = base + ((t & 1) ? OFF_F1 : OFF_F0);

        // S = L @ Q^T  (warp: 16 rows x 64 q-cols)
        float sacc[8][4];
#pragma unroll
        for (int j = 0; j < 8; j++)
#pragma unroll
            for (int i = 0; i < 4; i++) sacc[j][i] = 0.f;
#pragma unroll
        for (int kk = 0; kk < 8; kk++) {
#pragma unroll
            for (int jp = 0; jp < 4; jp++) {
                uint32_t Bq[4];
                ldsm4(Bq, bufQ + (uint32_t)((c * 64 + 16 * jp + 8 * asel + brow) * 272
                                            + (kk * 16 + bsel * 8) * 2));
                mma_f16(sacc[2 * jp],     Lf[kk], Bq);
                mma_f16(sacc[2 * jp + 1], Lf[kk], Bq + 2);
            }
        }

        // mask + partial row max
        float ma = -1e30f, mb = -1e30f;
#pragma unroll
        for (int j = 0; j < 8; j++) {
            float2 md = *(float2*)(maddSm + t * 128 + c * 64 + 8 * j + 2 * qd);
            sacc[j][0] += md.x; sacc[j][1] += md.y;
            sacc[j][2] += md.x; sacc[j][3] += md.y;
            ma = fmaxf(ma, fmaxf(sacc[j][0], sacc[j][1]));
            mb = fmaxf(mb, fmaxf(sacc[j][2], sacc[j][3]));
        }
        ma = fmaxf(ma, __shfl_xor_sync(0xffffffffu, ma, 1));
        ma = fmaxf(ma, __shfl_xor_sync(0xffffffffu, ma, 2));
        mb = fmaxf(mb, __shfl_xor_sync(0xffffffffu, mb, 1));
        mb = fmaxf(mb, __shfl_xor_sync(0xffffffffu, mb, 2));
        if (qd == 0) {
            rmaxSm[rowa * 2 + c] = ma;
            rmaxSm[(rowa + 8) * 2 + c] = mb;
        }
        __syncthreads();
        float fa = fmaxf(rmaxSm[rowa * 2], rmaxSm[rowa * 2 + 1]);
        float fb = fmaxf(rmaxSm[(rowa + 8) * 2], rmaxSm[(rowa + 8) * 2 + 1]);

        float m2a_n = fmaxf(m2a, fa * L2E);
        float m2b_n = fmaxf(m2b, fb * L2E);
        float ca = ex2f(m2a - m2a_n);
        float cb = ex2f(m2b - m2b_n);
        m2a = m2a_n; m2b = m2b_n;

        // rescale O (warp's own rows/cols)
#pragma unroll
        for (int j = 0; j < 8; j++) {
            o_acc[j][0] *= ca; o_acc[j][1] *= ca;
            o_acc[j][2] *= cb; o_acc[j][3] *= cb;
        }

        // P = exp2(S*log2e - m2) -> Psm (f16), partial row sums
        float psa = 0.f, psb = 0.f;
#pragma unroll
        for (int j = 0; j < 8; j++) {
            int col = c * 64 + 8 * j + 2 * qd;
            float x0 = fmaf(sacc[j][0], L2E, -m2a);
            float x1 = fmaf(sacc[j][1], L2E, -m2a);
            float x2 = fmaf(sacc[j][2], L2E, -m2b);
            float x3 = fmaf(sacc[j][3], L2E, -m2b);
            __half2 pa2 = h2exp2(__floats2half2_rn(x0, x1));
            __half2 pb2 = h2exp2(__floats2half2_rn(x2, x3));
            *(__half2*)(sm + OFF_P + rowa * 272 + col * 2) = pa2;
            *(__half2*)(sm + OFF_P + (rowa + 8) * 272 + col * 2) = pb2;
            float2 fa2 = __half22float2(pa2);
            float2 fb2 = __half22float2(pb2);
            psa += fa2.x + fa2.y;
            psb += fb2.x + fb2.y;
        }
        psa += __shfl_xor_sync(0xffffffffu, psa, 1);
        psa += __shfl_xor_sync(0xffffffffu, psa, 2);
        psb += __shfl_xor_sync(0xffffffffu, psb, 1);
        psb += __shfl_xor_sync(0xffffffffu, psb, 2);
        if (qd == 0) {
            rsumSm[rowa * 2 + c] = psa;
            rsumSm[(rowa + 8) * 2 + c] = psb;
        }
        __syncthreads();
        sra = sra * ca + rsumSm[rowa * 2] + rsumSm[rowa * 2 + 1];
        srb = srb * cb + rsumSm[(rowa + 8) * 2] + rsumSm[(rowa + 8) * 2 + 1];

        // O += P @ Q (Pf a-frags from Psm; B via ldmatrix.trans on Q tile)
#pragma unroll
        for (int kk = 0; kk < 8; kk++) {
            uint32_t Pf[4];
            ldsm4(Pf, base + OFF_P + (uint32_t)((s * 16 + (l & 15)) * 272
                                                + (kk * 16 + asel * 8) * 2));
#pragma unroll
            for (int jp = 0; jp < 4; jp++) {
                uint32_t Bv[4];
                ldsm4t(Bv, bufQ + (uint32_t)((kk * 16 + bsel * 8 + brow) * 272
                                             + (c * 64 + 16 * jp + 8 * asel) * 2));
                mma_f16(o_acc[2 * jp],     Pf, Bv);
                mma_f16(o_acc[2 * jp + 1], Pf, Bv + 2);
            }
        }

        __syncthreads();   // done reading buf[t&1] and Psm; safe to refill
        if (t + 2 < 4) {
            const int tn = t + 2;
            uint32_t buf = base + ((tn & 1) ? OFF_F1 : OFF_F0);
#pragma unroll
            for (int it = 0; it < 4; it++) {
                int idx = tid + it * 512;
                int row = idx >> 4, seg = idx & 15;
                cpa16(buf + row * 272 + seg * 16,
                      gq + (size_t)(tn * 128 + row) * H_DIM + seg * 8);
            }
            CP_COMMIT();
        }
    }

    // ---------------- normalize + store -------------------------------------
    const float ia = 1.f / sra, ib = 1.f / srb;
    const int r0 = c0 + rowa;
    float* ob = out + (size_t)b * CTXN * H_DIM;
#pragma unroll
    for (int j = 0; j < 8; j++) {
        int col = c * 64 + 8 * j + 2 * qd;
        float2 v0 = make_float2(o_acc[j][0] * ia, o_acc[j][1] * ia);
        float2 v1 = make_float2(o_acc[j][2] * ib, o_acc[j][3] * ib);
        *(float2*)(ob + (size_t)r0 * H_DIM + col) = v0;
        *(float2*)(ob + (size_t)(r0 + 8) * H_DIM + col) = v1;
    }
}

// ---------------------------------------------------------------------------
extern "C" void kernel_launch(void* const* d_in, const int* in_sizes, int n_in,
                              void* d_out, int out_size) {
    const float* ctx  = (const float*)d_in[0];
    const float* qst  = (const float*)d_in[1];
    const int*   mask = (const int*)d_in[2];
    const float* W    = (const float*)d_in[3];
    const float* bias = (const float*)d_in[4];
    float* out = (float*)d_out;

    cudaFuncSetAttribute(qst_logits_kernel,
                         cudaFuncAttributeMaxDynamicSharedMemorySize, SM1_BYTES);
    cudaFuncSetAttribute(attn_kernel,
                         cudaFuncAttributeMaxDynamicSharedMemorySize, SM2_BYTES);

    qst_logits_kernel<<<(B_ * QSTN) / 32, 256, SM1_BYTES>>>(qst, W, bias);
    attn_kernel<<<dim3(CTXN / 128, B_), 512, SM2_BYTES>>>(ctx, mask, W, bias, out);
}

// round 16
// speedup vs baseline: 1.7827x; 1.7827x over previous
#include <cuda_runtime.h>
#include <cuda_fp16.h>
#include <cuda_bf16.h>
#include <cstdint>

#define B_    8
#define CTXN  4096
#define QSTN  512
#define E_DIM 300
#define EPAD  320
#define H_DIM 128
#define L2E   1.44269504088896340736f

// f16 qst logits, [q,h] layout (1 MB)
__device__ __align__(16) __half g_Q[B_ * QSTN * H_DIM];

// ---------------------------------------------------------------------------
// helpers
// ---------------------------------------------------------------------------
__device__ __forceinline__ uint32_t smem_u32(const void* p) {
    uint32_t a;
    asm("{ .reg .u64 t; cvta.to.shared.u64 t, %1; cvt.u32.u64 %0, t; }" : "=r"(a) : "l"(p));
    return a;
}
__device__ __forceinline__ void ldsm4(uint32_t* r, uint32_t addr) {
    asm volatile("ldmatrix.sync.aligned.m8n8.x4.shared.b16 {%0,%1,%2,%3}, [%4];"
                 : "=r"(r[0]), "=r"(r[1]), "=r"(r[2]), "=r"(r[3]) : "r"(addr));
}
__device__ __forceinline__ void ldsm4t(uint32_t* r, uint32_t addr) {
    asm volatile("ldmatrix.sync.aligned.m8n8.x4.trans.shared.b16 {%0,%1,%2,%3}, [%4];"
                 : "=r"(r[0]), "=r"(r[1]), "=r"(r[2]), "=r"(r[3]) : "r"(addr));
}
__device__ __forceinline__ void mma_f16(float* c, const uint32_t* a, const uint32_t* b) {
    asm volatile("mma.sync.aligned.m16n8k16.row.col.f32.f16.f16.f32 "
                 "{%0,%1,%2,%3}, {%4,%5,%6,%7}, {%8,%9}, {%0,%1,%2,%3};"
                 : "+f"(c[0]), "+f"(c[1]), "+f"(c[2]), "+f"(c[3])
                 : "r"(a[0]), "r"(a[1]), "r"(a[2]), "r"(a[3]), "r"(b[0]), "r"(b[1]));
}
__device__ __forceinline__ float ex2f(float x) {
    float y; asm("ex2.approx.f32 %0, %1;" : "=f"(y) : "f"(x)); return y;
}
__device__ __forceinline__ void cpa16(uint32_t dst, const void* src) {
    asm volatile("cp.async.cg.shared.global [%0], [%1], 16;" :: "r"(dst), "l"(src));
}
#define CP_COMMIT() asm volatile("cp.async.commit_group;")

// split float4 into packed f16 hi/lo (2x uint2)
__device__ __forceinline__ void split4h(float4 v, uint2& hv, uint2& lv) {
    float t[4] = {v.x, v.y, v.z, v.w};
    uint32_t hh[2], ll[2];
#pragma unroll
    for (int p = 0; p < 2; p++) {
        __half a = __float2half_rn(t[2 * p]);
        __half c = __float2half_rn(t[2 * p + 1]);
        __half2 h2; h2.x = a; h2.y = c;
        __half2 l2;
        l2.x = __float2half_rn(t[2 * p] - __half2float(a));
        l2.y = __float2half_rn(t[2 * p + 1] - __half2float(c));
        hh[p] = *reinterpret_cast<uint32_t*>(&h2);
        ll[p] = *reinterpret_cast<uint32_t*>(&l2);
    }
    hv = make_uint2(hh[0], hh[1]);
    lv = make_uint2(ll[0], ll[1]);
}

// convert float4 -> packed f16 (uint2)
__device__ __forceinline__ uint2 cvt4h(float4 v) {
    __half2 h0 = __floats2half2_rn(v.x, v.y);
    __half2 h1 = __floats2half2_rn(v.z, v.w);
    return make_uint2(*reinterpret_cast<uint32_t*>(&h0),
                      *reinterpret_cast<uint32_t*>(&h1));
}

// ---------------------------------------------------------------------------
// Kernel 1: qst logits via HMMA (f16 A-split 2-pass). 1 CTA = 32 q-rows, 8 warps.
// (unchanged — keeps full Q-side accuracy)
// ---------------------------------------------------------------------------
#define WPITCH 656
#define OFF1_A 0
#define OFF1_W 41984
#define OFF1_T 125952
#define SM1_BYTES 134656
#define K1_TP 136

__global__ __launch_bounds__(256, 1)
void qst_logits_kernel(const float* __restrict__ qst,
                       const float* __restrict__ W,
                       const float* __restrict__ bias) {
    extern __shared__ char sm[];
    const uint32_t base = smem_u32(sm);
    const int tid = threadIdx.x, w = tid >> 5, l = tid & 31;
    const int s = w & 1, c = w >> 1;
    const int grp = l >> 2, qd = l & 3;
    const int asel = (l >> 4) & 1, bsel = (l >> 3) & 1, brow = l & 7;
    const int row0 = blockIdx.x * 32;

#pragma unroll
    for (int it = 0; it < 40; it++) {
        int idx = tid + it * 256;
        int row = idx / 80, seg = idx - row * 80;
        float4 v = make_float4(0.f, 0.f, 0.f, 0.f);
        if (seg < 75)
            v = *(const float4*)(W + (size_t)row * E_DIM + seg * 4);
        *(uint2*)(sm + OFF1_W + row * WPITCH + seg * 8) = cvt4h(v);
    }

#pragma unroll
    for (int it = 0; it < 10; it++) {
        int idx = tid + it * 256;
        int row = idx / 80, seg = idx - row * 80;
        float4 v = make_float4(0.f, 0.f, 0.f, 0.f);
        if (seg < 75)
            v = *(const float4*)(qst + (size_t)(row0 + row) * E_DIM + seg * 4);
        uint2 hv, lv;
        split4h(v, hv, lv);
        *(uint2*)(sm + OFF1_A + row * WPITCH + seg * 8) = hv;
        *(uint2*)(sm + OFF1_A + 20992 + row * WPITCH + seg * 8) = lv;
    }
    __syncthreads();

    float acc[4][4];
#pragma unroll
    for (int j = 0; j < 4; j++)
#pragma unroll
        for (int i = 0; i < 4; i++) acc[j][i] = 0.f;

    const uint32_t arow = (uint32_t)(s * 16 + (l & 15));
#pragma unroll
    for (int kk = 0; kk < 19; kk++) {
        uint32_t Ah[4], Al[4];
        uint32_t aoff = arow * WPITCH + (uint32_t)((kk * 16 + asel * 8) * 2);
        ldsm4(Ah, base + OFF1_A + aoff);
        ldsm4(Al, base + OFF1_A + 20992 + aoff);
#pragma unroll
        for (int jp = 0; jp < 2; jp++) {
            uint32_t Bw[4];
            uint32_t boff = (uint32_t)((c * 32 + 16 * jp + 8 * asel + brow) * WPITCH
                                       + (kk * 16 + bsel * 8) * 2);
            ldsm4(Bw, base + OFF1_W + boff);
            mma_f16(acc[2 * jp],     Ah, Bw);
            mma_f16(acc[2 * jp],     Al, Bw);
            mma_f16(acc[2 * jp + 1], Ah, Bw + 2);
            mma_f16(acc[2 * jp + 1], Al, Bw + 2);
        }
    }

    __half* sT = (__half*)(sm + OFF1_T);
    const int rowa = s * 16 + grp;
#pragma unroll
    for (int j = 0; j < 4; j++) {
        int col = c * 32 + 8 * j + 2 * qd;
        float b0 = bias[col], b1 = bias[col + 1];
        sT[rowa * K1_TP + col]     = __float2half_rn(fmaxf(acc[j][0] + b0, 0.f));
        sT[rowa * K1_TP + col + 1] = __float2half_rn(fmaxf(acc[j][1] + b1, 0.f));
        sT[(rowa + 8) * K1_TP + col]     = __float2half_rn(fmaxf(acc[j][2] + b0, 0.f));
        sT[(rowa + 8) * K1_TP + col + 1] = __float2half_rn(fmaxf(acc[j][3] + b1, 0.f));
    }
    __syncthreads();

    for (int idx = tid; idx < 32 * 16; idx += 256) {
        int r = idx >> 4, seg = idx & 15;
        uint4 v = *(uint4*)(sT + r * K1_TP + seg * 8);
        *(uint4*)(g_Q + (size_t)(row0 + r) * H_DIM + seg * 8) = v;
    }
}

// ---------------------------------------------------------------------------
// Kernel 2: HMMA fused dense + flash attention. 1 CTA = 128 ctx rows, 8 warps.
// Phase-1: ctx single f16 (no split), A chunks double-buffered (1 sync/chunk).
// Flash loop = proven R12 configuration.
// ---------------------------------------------------------------------------
#define OFF_BIAS 0
#define OFF_MADD 512
#define OFF_A    4864       // A buf0 18432, buf1 +18432 -> end 41728
#define OFF_W    41728      // W f16 83968 -> end 125696
#define OFF_F0   4864       // flash buf0 (34816) reuses A region
#define OFF_F1   39680      // flash buf1 -> end 74496
#define SM2_BYTES 125696

__global__ __launch_bounds__(256, 1)
void attn_kernel(const float* __restrict__ ctx,
                 const int* __restrict__ mask,
                 const float* __restrict__ W,
                 const float* __restrict__ bias,
                 float* __restrict__ out) {
    extern __shared__ char sm[];
    const uint32_t base = smem_u32(sm);
    const int tid = threadIdx.x, w = tid >> 5, l = tid & 31;
    const int grp = l >> 2, qd = l & 3;
    const int asel = (l >> 4) & 1, bsel = (l >> 3) & 1, brow = l & 7;
    const int b = blockIdx.y, c0 = blockIdx.x * 128;

    // whole W converted float->f16 into smem (L2-hot after first CTA)
#pragma unroll
    for (int it = 0; it < 40; it++) {
        int idx = tid + it * 256;
        int row = idx / 80, seg = idx - row * 80;
        float4 v = make_float4(0.f, 0.f, 0.f, 0.f);
        if (seg < 75)
            v = *(const float4*)(W + (size_t)row * E_DIM + seg * 4);
        *(uint2*)(sm + OFF_W + row * WPITCH + seg * 8) = cvt4h(v);
    }

    float* biasSm = (float*)(sm + OFF_BIAS);
    float* maddSm = (float*)(sm + OFF_MADD);
    for (int i = tid; i < H_DIM; i += 256) biasSm[i] = bias[i];
    for (int i = tid; i < QSTN; i += 256)
        maddSm[i] = mask[b * QSTN + i] ? 0.f : -2e30f;

    const float* ctxb = ctx + ((size_t)b * CTXN + c0) * E_DIM;

    // stage chunk 0 directly (load + convert) into buf0
#pragma unroll
    for (int it = 0; it < 8; it++) {
        int idx = tid + it * 256;
        int row = idx >> 4, c4 = idx & 15;
        float4 v = *(const float4*)(ctxb + (size_t)row * E_DIM + c4 * 4);
        *(uint2*)(sm + OFF_A + row * 144 + c4 * 8) = cvt4h(v);
    }
    __syncthreads();

    // prefetch chunk 1
    float4 pa[8];
#pragma unroll
    for (int it = 0; it < 8; it++) {
        int idx = tid + it * 256;
        int row = idx >> 4, c4 = idx & 15;
        pa[it] = *(const float4*)(ctxb + (size_t)row * E_DIM + 64 + c4 * 4);
    }

    // ---------------- Phase 1: acc = ctx_tile @ W^T (single f16 A) ----------
    float acc[16][4];
#pragma unroll
    for (int j = 0; j < 16; j++)
#pragma unroll
        for (int i = 0; i < 4; i++) acc[j][i] = 0.f;

    const uint32_t arow = (uint32_t)(w * 16 + (l & 15));

    for (int ck = 0; ck < 5; ck++) {
        // stage chunk ck+1 into the other ping-pong buffer
        if (ck < 4) {
            char* bufn = sm + OFF_A + ((ck + 1) & 1) * 18432;
#pragma unroll
            for (int it = 0; it < 8; it++) {
                int idx = tid + it * 256;
                int row = idx >> 4, c4 = idx & 15;
                *(uint2*)(bufn + row * 144 + c4 * 8) = cvt4h(pa[it]);
            }
        }
        // prefetch chunk ck+2 (2 deep)
        if (ck < 3) {
            const int cc = ck + 2;
#pragma unroll
            for (int it = 0; it < 8; it++) {
                int idx = tid + it * 256;
                int row = idx >> 4, c4 = idx & 15;
                float4 v = make_float4(0.f, 0.f, 0.f, 0.f);
                if (cc < 4 || c4 < 11)
                    v = *(const float4*)(ctxb + (size_t)row * E_DIM + cc * 64 + c4 * 4);
                pa[it] = v;
            }
        }

        const uint32_t bufA = base + OFF_A + (uint32_t)((ck & 1) * 18432);
        const int nks = (ck < 4) ? 4 : 3;    // skip all-zero cols 304-319
#pragma unroll
        for (int kk = 0; kk < 4; kk++) {
            if (kk >= nks) break;
            const int gk = ck * 4 + kk;
            uint32_t Af[4];
            ldsm4(Af, bufA + arow * 144 + (uint32_t)((kk * 16 + asel * 8) * 2));
#pragma unroll
            for (int jp = 0; jp < 8; jp++) {
                uint32_t Bw[4];
                uint32_t boff = (uint32_t)((16 * jp + 8 * asel + brow) * WPITCH
                                           + (gk * 16 + bsel * 8) * 2);
                ldsm4(Bw, base + OFF_W + boff);
                mma_f16(acc[2 * jp],     Af, Bw);
                mma_f16(acc[2 * jp + 1], Af, Bw + 2);
            }
        }
        __syncthreads();
    }

    // ---------------- bias + relu -> L fragments (f16, registers) ----------
    uint32_t Lf[8][4];
#pragma unroll
    for (int j = 0; j < 16; j++) {
        float2 bb = *(float2*)(biasSm + 8 * j + 2 * qd);
        float v0 = fmaxf(acc[j][0] + bb.x, 0.f);
        float v1 = fmaxf(acc[j][1] + bb.y, 0.f);
        float v2 = fmaxf(acc[j][2] + bb.x, 0.f);
        float v3 = fmaxf(acc[j][3] + bb.y, 0.f);
        __half2 ha = __floats2half2_rn(v0, v1);
        __half2 hb = __floats2half2_rn(v2, v3);
        Lf[j >> 1][(j & 1) * 2]     = *reinterpret_cast<uint32_t*>(&ha);
        Lf[j >> 1][(j & 1) * 2 + 1] = *reinterpret_cast<uint32_t*>(&hb);
    }

    // ---------------- Flash loop: cp.async double-buffered Q tiles ----------
    const __half* gq = g_Q + (size_t)b * QSTN * H_DIM;

#pragma unroll
    for (int t0 = 0; t0 < 2; t0++) {
        uint32_t buf = base + (t0 ? OFF_F1 : OFF_F0);
#pragma unroll
        for (int it = 0; it < 8; it++) {
            int idx = tid + it * 256;
            int row = idx >> 4, seg = idx & 15;
            cpa16(buf + row * 272 + seg * 16,
                  gq + (size_t)(t0 * 128 + row) * H_DIM + seg * 8);
        }
        CP_COMMIT();
    }

    float m2a = -1e30f, m2b = -1e30f, sra = 0.f, srb = 0.f;
    float o_acc[16][4];
#pragma unroll
    for (int j = 0; j < 16; j++)
#pragma unroll
        for (int i = 0; i < 4; i++) o_acc[j][i] = 0.f;

    for (int t = 0; t < 4; t++) {
        if (t < 3) asm volatile("cp.async.wait_group 1;");
        else       asm volatile("cp.async.wait_group 0;");
        __syncthreads();
        const uint32_t bufQ = base + ((t & 1) ? OFF_F1 : OFF_F0);

        // S = L @ Q^T
        float sacc[16][4];
#pragma unroll
        for (int j = 0; j < 16; j++)
#pragma unroll
            for (int i = 0; i < 4; i++) sacc[j][i] = 0.f;
#pragma unroll
        for (int kk = 0; kk < 8; kk++) {
#pragma unroll
            for (int jp = 0; jp < 8; jp++) {
                uint32_t Bq[4];
                ldsm4(Bq, bufQ + (uint32_t)((16 * jp + 8 * asel + brow) * 272
                                            + (kk * 16 + bsel * 8) * 2));
                mma_f16(sacc[2 * jp],     Lf[kk], Bq);
                mma_f16(sacc[2 * jp + 1], Lf[kk], Bq + 2);
            }
        }

        // mask + row max
        float ma = -1e30f, mb = -1e30f;
#pragma unroll
        for (int j = 0; j < 16; j++) {
            float2 md = *(float2*)(maddSm + t * 128 + 8 * j + 2 * qd);
            sacc[j][0] += md.x; sacc[j][1] += md.y;
            sacc[j][2] += md.x; sacc[j][3] += md.y;
            ma = fmaxf(ma, fmaxf(sacc[j][0], sacc[j][1]));
            mb = fmaxf(mb, fmaxf(sacc[j][2], sacc[j][3]));
        }
        ma = fmaxf(ma, __shfl_xor_sync(0xffffffffu, ma, 1));
        ma = fmaxf(ma, __shfl_xor_sync(0xffffffffu, ma, 2));
        mb = fmaxf(mb, __shfl_xor_sync(0xffffffffu, mb, 1));
        mb = fmaxf(mb, __shfl_xor_sync(0xffffffffu, mb, 2));

        float m2a_n = fmaxf(m2a, ma * L2E);
        float m2b_n = fmaxf(m2b, mb * L2E);
        float ca = ex2f(m2a - m2a_n);
        float cb = ex2f(m2b - m2b_n);
        m2a = m2a_n; m2b = m2b_n;

        // rescale O first (independent of P)
#pragma unroll
        for (int j = 0; j < 16; j++) {
            o_acc[j][0] *= ca; o_acc[j][1] *= ca;
            o_acc[j][2] *= cb; o_acc[j][3] *= cb;
        }

        // streamed P: build each kk's fragment, immediately feed its PV mmas
        float psa = 0.f, psb = 0.f;
#pragma unroll
        for (int kk = 0; kk < 8; kk++) {
            uint32_t Pk[4];
#pragma unroll
            for (int jj = 0; jj < 2; jj++) {
                const int j = 2 * kk + jj;
                float x0 = fmaf(sacc[j][0], L2E, -m2a);
                float x1 = fmaf(sacc[j][1], L2E, -m2a);
                float x2 = fmaf(sacc[j][2], L2E, -m2b);
                float x3 = fmaf(sacc[j][3], L2E, -m2b);
                __half2 pa2 = h2exp2(__floats2half2_rn(x0, x1));
                __half2 pb2 = h2exp2(__floats2half2_rn(x2, x3));
                Pk[jj * 2]     = *reinterpret_cast<uint32_t*>(&pa2);
                Pk[jj * 2 + 1] = *reinterpret_cast<uint32_t*>(&pb2);
                float2 fa = __half22float2(pa2);
                float2 fb = __half22float2(pb2);
                psa += fa.x + fa.y;
                psb += fb.x + fb.y;
            }
#pragma unroll
            for (int jp = 0; jp < 8; jp++) {
                uint32_t Bv[4];
                ldsm4t(Bv, bufQ + (uint32_t)((kk * 16 + bsel * 8 + brow) * 272
                                             + (16 * jp + 8 * asel) * 2));
                mma_f16(o_acc[2 * jp],     Pk, Bv);
                mma_f16(o_acc[2 * jp + 1], Pk, Bv + 2);
            }
        }
        psa += __shfl_xor_sync(0xffffffffu, psa, 1);
        psa += __shfl_xor_sync(0xffffffffu, psa, 2);
        psb += __shfl_xor_sync(0xffffffffu, psb, 1);
        psb += __shfl_xor_sync(0xffffffffu, psb, 2);
        sra = sra * ca + psa;
        srb = srb * cb + psb;

        __syncthreads();   // done reading buf[t&1]; safe to refill
        if (t + 2 < 4) {
            const int tn = t + 2;
            uint32_t buf = base + ((tn & 1) ? OFF_F1 : OFF_F0);
#pragma unroll
            for (int it = 0; it < 8; it++) {
                int idx = tid + it * 256;
                int row = idx >> 4, seg = idx & 15;
                cpa16(buf + row * 272 + seg * 16,
                      gq + (size_t)(tn * 128 + row) * H_DIM + seg * 8);
            }
            CP_COMMIT();
        }
    }

    // ---------------- normalize + store -------------------------------------
    const float ia = 1.f / sra, ib = 1.f / srb;
    const int r0 = c0 + w * 16 + grp;
    float* ob = out + (size_t)b * CTXN * H_DIM;
#pragma unroll
    for (int j = 0; j < 16; j++) {
        int col = 8 * j + 2 * qd;
        float2 v0 = make_float2(o_acc[j][0] * ia, o_acc[j][1] * ia);
        float2 v1 = make_float2(o_acc[j][2] * ib, o_acc[j][3] * ib);
        *(float2*)(ob + (size_t)r0 * H_DIM + col) = v0;
        *(float2*)(ob + (size_t)(r0 + 8) * H_DIM + col) = v1;
    }
}

// ---------------------------------------------------------------------------
extern "C" void kernel_launch(void* const* d_in, const int* in_sizes, int n_in,
                              void* d_out, int out_size) {
    const float* ctx  = (const float*)d_in[0];
    const float* qst  = (const float*)d_in[1];
    const int*   mask = (const int*)d_in[2];
    const float* W    = (const float*)d_in[3];
    const float* bias = (const float*)d_in[4];
    float* out = (float*)d_out;

    cudaFuncSetAttribute(qst_logits_kernel,
                         cudaFuncAttributeMaxDynamicSharedMemorySize, SM1_BYTES);
    cudaFuncSetAttribute(attn_kernel,
                         cudaFuncAttributeMaxDynamicSharedMemorySize, SM2_BYTES);

    qst_logits_kernel<<<(B_ * QSTN) / 32, 256, SM1_BYTES>>>(qst, W, bias);
    attn_kernel<<<dim3(CTXN / 128, B_), 256, SM2_BYTES>>>(ctx, mask, W, bias, out);
}